// round 1
// baseline (speedup 1.0000x reference)
#include <cuda_runtime.h>
#include <cstdint>
#include <cstddef>

#define BB 8
#define LL 2048
#define HH 256
#define ROWS 32
#define JT 64
#define NT (LL / JT)

// -------- scratch (no allocations allowed: __device__ globals) --------
__device__ float g_base[LL];        // 1/log2(2+d), d==0 -> 0.5
__device__ float g_st[BB * LL];     // tanh(text@Wt^T+bt) . wa[:H]
__device__ float g_so[BB * LL];     // tanh(op@Wo^T) . wa[H:] + ba
__device__ float g_mult[BB * LL];   // 8 if opinion tag else 1

// ---------------------------------------------------------------------
// Kernel 0: base table + per-token column multiplier
// ---------------------------------------------------------------------
__global__ void k_base_mult(const int* __restrict__ pos) {
    int i = blockIdx.x * blockDim.x + threadIdx.x;
    if (i < LL) {
        g_base[i] = (i == 0) ? 0.5f : (1.0f / log2f(2.0f + (float)i));
    }
    if (i < BB * LL) {
        const unsigned long long mask =
            (1ULL << 19) | (1ULL << 20) | (1ULL << 21) |
            (1ULL << 33) | (1ULL << 34) | (1ULL << 35) |
            (1ULL << 41) | (1ULL << 42) | (1ULL << 43) |
            (1ULL << 44) | (1ULL << 45) | (1ULL << 46);
        int p = pos[i];
        bool op = (p >= 0) && (p < 64) && (((mask >> p) & 1ULL) != 0ULL);
        g_mult[i] = op ? 8.0f : 1.0f;
    }
}

// ---------------------------------------------------------------------
// Kernel 1: per-token transform  out = tanh(X @ W^T + bias) . wa  (+extra)
// CTA: 32 tokens x 256 features, 256 threads, thread tile 4x8.
// which==0 -> g_st, which==1 -> g_so
// ---------------------------------------------------------------------
__global__ __launch_bounds__(256, 1)
void k_transform(const float* __restrict__ X, const float* __restrict__ W,
                 const float* __restrict__ bias, const float* __restrict__ wav,
                 const float* __restrict__ extra_ptr, int which) {
    __shared__ float Ws[256 * 33];   // [h][k] padded: bank = tx + k  (conflict-free)
    __shared__ float Xs[32 * 32];    // [tok][k]
    __shared__ float bias_s[256];
    __shared__ float wa_s[256];

    int tid = threadIdx.x;
    int tx = tid & 31, ty = tid >> 5;
    int tok0 = blockIdx.x * 32;

    bias_s[tid] = bias ? bias[tid] : 0.0f;
    wa_s[tid] = wav[tid];

    float acc[4][8];
#pragma unroll
    for (int q = 0; q < 4; ++q)
#pragma unroll
        for (int m = 0; m < 8; ++m) acc[q][m] = 0.0f;

    for (int k0 = 0; k0 < 256; k0 += 32) {
        __syncthreads();
        // W chunk: 256 h x 32 k  (coalesced reads, padded store)
#pragma unroll
        for (int r = 0; r < 32; ++r) {
            int idx = r * 256 + tid;
            int h = idx >> 5, kk = idx & 31;
            Ws[h * 33 + kk] = W[h * 256 + k0 + kk];
        }
        // X chunk: 32 tok x 32 k
#pragma unroll
        for (int r = 0; r < 4; ++r) {
            int idx = r * 256 + tid;
            int tok = idx >> 5, kk = idx & 31;
            Xs[idx] = X[(size_t)(tok0 + tok) * 256 + k0 + kk];
        }
        __syncthreads();
#pragma unroll 8
        for (int kk = 0; kk < 32; ++kk) {
            float wv[8], xv[4];
#pragma unroll
            for (int m = 0; m < 8; ++m) wv[m] = Ws[(tx + 32 * m) * 33 + kk];
#pragma unroll
            for (int q = 0; q < 4; ++q) xv[q] = Xs[(ty * 4 + q) * 32 + kk];
#pragma unroll
            for (int q = 0; q < 4; ++q)
#pragma unroll
                for (int m = 0; m < 8; ++m)
                    acc[q][m] = fmaf(xv[q], wv[m], acc[q][m]);
        }
    }

    float e = extra_ptr ? extra_ptr[0] : 0.0f;
    float part[4];
#pragma unroll
    for (int q = 0; q < 4; ++q) {
        float s = 0.0f;
#pragma unroll
        for (int m = 0; m < 8; ++m) {
            int h = tx + 32 * m;
            s += tanhf(acc[q][m] + bias_s[h]) * wa_s[h];
        }
        part[q] = s;
    }
#pragma unroll
    for (int off = 16; off; off >>= 1) {
#pragma unroll
        for (int q = 0; q < 4; ++q)
            part[q] += __shfl_xor_sync(0xffffffffu, part[q], off);
    }
    if (tx == 0) {
        float* outp = which ? g_so : g_st;
#pragma unroll
        for (int q = 0; q < 4; ++q)
            outp[tok0 + ty * 4 + q] = part[q] + e;
    }
}

// ---------------------------------------------------------------------
// Kernel 2: flash-style attention.
// CTA = 32 rows of one batch; j tiled by 64 with cp.async double buffer.
// scores_ij = (st_i + so_j) * base(|i-j|) * mult_j ; online softmax; PV fp32.
// ---------------------------------------------------------------------
__device__ __forceinline__ void cp16(float* s, const float* g) {
    unsigned sa = (unsigned)__cvta_generic_to_shared(s);
    asm volatile("cp.async.cg.shared.global [%0], [%1], 16;\n" ::"r"(sa), "l"(g));
}

__global__ __launch_bounds__(256, 1)
void k_attn(const float* __restrict__ V, float* __restrict__ out) {
    extern __shared__ float sm[];
    float* Vs = sm;                       // 2 * 64 * 256
    float* Ps = Vs + 2 * JT * HH;         // 32 * 64
    float* base_s = Ps + ROWS * JT;       // 2048
    float* M_s = base_s + LL;             // 32
    float* S_s = M_s + ROWS;              // 32
    float* F_s = S_s + ROWS;              // 32

    int tid = threadIdx.x;
    int tx = tid & 31, ty = tid >> 5;
    int b = blockIdx.x >> 6;
    int row0 = (blockIdx.x & 63) * ROWS;

    const float* Vg = V + (size_t)b * LL * HH;
    const float* sog = g_so + b * LL;
    const float* mug = g_mult + b * LL;

    for (int i = tid; i < LL; i += 256) base_s[i] = g_base[i];
    if (tid < ROWS) { M_s[tid] = -1e30f; S_s[tid] = 0.0f; }

    // prefetch tile 0 into buffer 0
#pragma unroll
    for (int r = 0; r < (JT * HH / 4) / 256; ++r) {
        int c = r * 256 + tid;
        cp16(Vs + c * 4, Vg + c * 4);
    }
    asm volatile("cp.async.commit_group;\n");

    int sr = tid >> 3;            // score row 0..31
    int sjo = (tid & 7) * 8;      // 8 consecutive j per thread
    float sti = g_st[b * LL + row0 + sr];
    int gi = row0 + sr;

    float4 acc[4][2];
#pragma unroll
    for (int q = 0; q < 4; ++q) {
        acc[q][0] = make_float4(0.f, 0.f, 0.f, 0.f);
        acc[q][1] = make_float4(0.f, 0.f, 0.f, 0.f);
    }

    __syncthreads();  // base_s / M_s / S_s ready

    for (int t = 0; t < NT; ++t) {
        if (t) __syncthreads();   // protect Ps/M_s/S_s vs previous PV readers
        int j0 = t * JT;

        // ---- score phase: 8 scores per thread ----
        float4 so0 = *(const float4*)(sog + j0 + sjo);
        float4 so1 = *(const float4*)(sog + j0 + sjo + 4);
        float4 mu0 = *(const float4*)(mug + j0 + sjo);
        float4 mu1 = *(const float4*)(mug + j0 + sjo + 4);
        float sov[8] = {so0.x, so0.y, so0.z, so0.w, so1.x, so1.y, so1.z, so1.w};
        float muv[8] = {mu0.x, mu0.y, mu0.z, mu0.w, mu1.x, mu1.y, mu1.z, mu1.w};

        float s[8];
        float lm = -1e30f;
#pragma unroll
        for (int u = 0; u < 8; ++u) {
            int j = j0 + sjo + u;
            int d = gi - j; d = (d < 0) ? -d : d;
            float sc = (sti + sov[u]) * base_s[d] * muv[u];
            s[u] = sc;
            lm = fmaxf(lm, sc);
        }
        lm = fmaxf(lm, __shfl_xor_sync(0xffffffffu, lm, 1));
        lm = fmaxf(lm, __shfl_xor_sync(0xffffffffu, lm, 2));
        lm = fmaxf(lm, __shfl_xor_sync(0xffffffffu, lm, 4));
        float Mold = M_s[sr];
        float Mn = fmaxf(Mold, lm);
        float ls = 0.0f;
#pragma unroll
        for (int u = 0; u < 8; ++u) {
            float p = __expf(s[u] - Mn);
            Ps[sr * JT + sjo + u] = p;
            ls += p;
        }
        ls += __shfl_xor_sync(0xffffffffu, ls, 1);
        ls += __shfl_xor_sync(0xffffffffu, ls, 2);
        ls += __shfl_xor_sync(0xffffffffu, ls, 4);
        if ((tid & 7) == 0) {
            float f = __expf(Mold - Mn);   // 0 on first tile
            F_s[sr] = f;
            M_s[sr] = Mn;
            S_s[sr] = S_s[sr] * f + ls;
        }

        // ---- prefetch next V tile ----
        if (t + 1 < NT) {
            float* Vn = Vs + ((t + 1) & 1) * JT * HH;
            const float* gs = Vg + (size_t)(j0 + JT) * HH;
#pragma unroll
            for (int r = 0; r < (JT * HH / 4) / 256; ++r) {
                int c = r * 256 + tid;
                cp16(Vn + c * 4, gs + c * 4);
            }
            asm volatile("cp.async.commit_group;\n");
            asm volatile("cp.async.wait_group 1;\n");
        } else {
            asm volatile("cp.async.wait_group 0;\n");
        }
        __syncthreads();  // V tile + Ps + F_s visible

        // ---- PV phase: acc(4 rows x 8 feats) += P @ V ----
        const float4* V4 = (const float4*)(Vs + (t & 1) * JT * HH);
        float f0 = F_s[ty * 4 + 0], f1 = F_s[ty * 4 + 1];
        float f2 = F_s[ty * 4 + 2], f3 = F_s[ty * 4 + 3];
        float fq[4] = {f0, f1, f2, f3};
#pragma unroll
        for (int q = 0; q < 4; ++q) {
            acc[q][0].x *= fq[q]; acc[q][0].y *= fq[q];
            acc[q][0].z *= fq[q]; acc[q][0].w *= fq[q];
            acc[q][1].x *= fq[q]; acc[q][1].y *= fq[q];
            acc[q][1].z *= fq[q]; acc[q][1].w *= fq[q];
        }
        const float* Pr0 = Ps + (ty * 4 + 0) * JT;
        const float* Pr1 = Ps + (ty * 4 + 1) * JT;
        const float* Pr2 = Ps + (ty * 4 + 2) * JT;
        const float* Pr3 = Ps + (ty * 4 + 3) * JT;
#pragma unroll 4
        for (int j = 0; j < JT; ++j) {
            float4 v0 = V4[j * 64 + tx * 2];
            float4 v1 = V4[j * 64 + tx * 2 + 1];
            float p0 = Pr0[j], p1 = Pr1[j], p2 = Pr2[j], p3 = Pr3[j];
            acc[0][0].x = fmaf(p0, v0.x, acc[0][0].x);
            acc[0][0].y = fmaf(p0, v0.y, acc[0][0].y);
            acc[0][0].z = fmaf(p0, v0.z, acc[0][0].z);
            acc[0][0].w = fmaf(p0, v0.w, acc[0][0].w);
            acc[0][1].x = fmaf(p0, v1.x, acc[0][1].x);
            acc[0][1].y = fmaf(p0, v1.y, acc[0][1].y);
            acc[0][1].z = fmaf(p0, v1.z, acc[0][1].z);
            acc[0][1].w = fmaf(p0, v1.w, acc[0][1].w);
            acc[1][0].x = fmaf(p1, v0.x, acc[1][0].x);
            acc[1][0].y = fmaf(p1, v0.y, acc[1][0].y);
            acc[1][0].z = fmaf(p1, v0.z, acc[1][0].z);
            acc[1][0].w = fmaf(p1, v0.w, acc[1][0].w);
            acc[1][1].x = fmaf(p1, v1.x, acc[1][1].x);
            acc[1][1].y = fmaf(p1, v1.y, acc[1][1].y);
            acc[1][1].z = fmaf(p1, v1.z, acc[1][1].z);
            acc[1][1].w = fmaf(p1, v1.w, acc[1][1].w);
            acc[2][0].x = fmaf(p2, v0.x, acc[2][0].x);
            acc[2][0].y = fmaf(p2, v0.y, acc[2][0].y);
            acc[2][0].z = fmaf(p2, v0.z, acc[2][0].z);
            acc[2][0].w = fmaf(p2, v0.w, acc[2][0].w);
            acc[2][1].x = fmaf(p2, v1.x, acc[2][1].x);
            acc[2][1].y = fmaf(p2, v1.y, acc[2][1].y);
            acc[2][1].z = fmaf(p2, v1.z, acc[2][1].z);
            acc[2][1].w = fmaf(p2, v1.w, acc[2][1].w);
            acc[3][0].x = fmaf(p3, v0.x, acc[3][0].x);
            acc[3][0].y = fmaf(p3, v0.y, acc[3][0].y);
            acc[3][0].z = fmaf(p3, v0.z, acc[3][0].z);
            acc[3][0].w = fmaf(p3, v0.w, acc[3][0].w);
            acc[3][1].x = fmaf(p3, v1.x, acc[3][1].x);
            acc[3][1].y = fmaf(p3, v1.y, acc[3][1].y);
            acc[3][1].z = fmaf(p3, v1.z, acc[3][1].z);
            acc[3][1].w = fmaf(p3, v1.w, acc[3][1].w);
        }
    }

    // ---- epilogue: normalize and store ----
    float4* O4 = (float4*)(out + ((size_t)b * LL + row0) * HH);
#pragma unroll
    for (int q = 0; q < 4; ++q) {
        int row = ty * 4 + q;
        float inv = 1.0f / S_s[row];
        float4 a0 = acc[q][0], a1 = acc[q][1];
        a0.x *= inv; a0.y *= inv; a0.z *= inv; a0.w *= inv;
        a1.x *= inv; a1.y *= inv; a1.z *= inv; a1.w *= inv;
        O4[(size_t)row * 64 + tx * 2] = a0;
        O4[(size_t)row * 64 + tx * 2 + 1] = a1;
    }
}

// ---------------------------------------------------------------------
extern "C" void kernel_launch(void* const* d_in, const int* in_sizes, int n_in,
                              void* d_out, int out_size) {
    const float* opinion = (const float*)d_in[0];
    const float* text    = (const float*)d_in[1];
    const int*   pos     = (const int*)d_in[2];
    const float* Wt      = (const float*)d_in[3];
    const float* bt      = (const float*)d_in[4];
    const float* Wo      = (const float*)d_in[5];
    const float* wa      = (const float*)d_in[6];
    const float* ba      = (const float*)d_in[7];
    float* out = (float*)d_out;

    const int attn_smem = (2 * JT * HH + ROWS * JT + LL + 3 * ROWS) * 4;
    cudaFuncSetAttribute(k_attn, cudaFuncAttributeMaxDynamicSharedMemorySize,
                         attn_smem);

    k_base_mult<<<(BB * LL + 255) / 256, 256>>>(pos);
    // st = tanh(text @ Wt^T + bt) . wa[:H]
    k_transform<<<BB * LL / 32, 256>>>(text, Wt, bt, wa, nullptr, 0);
    // so = tanh(opinion @ Wo^T) . wa[H:] + ba
    k_transform<<<BB * LL / 32, 256>>>(opinion, Wo, nullptr, wa + HH, ba, 1);
    k_attn<<<BB * (LL / ROWS), 256, attn_smem>>>(opinion, out);
}

// round 3
// speedup vs baseline: 2.5061x; 2.5061x over previous
#include <cuda_runtime.h>
#include <cstdint>
#include <cstddef>

#define BB 8
#define LL 2048
#define HH 256
#define ROWS 64
#define JT 64
#define NT (LL / JT)
#define PST 68            // Ps row stride (floats): 16B-aligned, kills 4-way STS conflict
#define WST 258           // Ws row stride in transform (even -> 8B-aligned pair loads)

typedef unsigned long long ull;

// -------- scratch (no allocations allowed: __device__ globals) --------
__device__ float g_base[LL];
__device__ float g_st[BB * LL];
__device__ float g_so[BB * LL];
__device__ float g_mult[BB * LL];

// ---------------------------------------------------------------------
// f32x2 helpers (Blackwell packed fp32 pipe)
// ---------------------------------------------------------------------
__device__ __forceinline__ ull pack_dup(float p) {
    ull r;
    asm("mov.b64 %0, {%1, %1};" : "=l"(r) : "f"(p));
    return r;
}
__device__ __forceinline__ void fma2(ull& d, ull a, ull b) {
    asm("fma.rn.f32x2 %0, %1, %2, %0;" : "+l"(d) : "l"(a), "l"(b));
}
__device__ __forceinline__ void mul2(ull& d, ull a) {
    asm("mul.rn.f32x2 %0, %0, %1;" : "+l"(d) : "l"(a));
}
__device__ __forceinline__ void unpack2(ull v, float& lo, float& hi) {
    asm("mov.b64 {%0, %1}, %2;" : "=f"(lo), "=f"(hi) : "l"(v));
}

// ---------------------------------------------------------------------
// Kernel 0: base table + per-token column multiplier
// ---------------------------------------------------------------------
__global__ void k_base_mult(const int* __restrict__ pos) {
    int i = blockIdx.x * blockDim.x + threadIdx.x;
    if (i < LL) {
        g_base[i] = (i == 0) ? 0.5f : (1.0f / log2f(2.0f + (float)i));
    }
    if (i < BB * LL) {
        const unsigned long long mask =
            (1ULL << 19) | (1ULL << 20) | (1ULL << 21) |
            (1ULL << 33) | (1ULL << 34) | (1ULL << 35) |
            (1ULL << 41) | (1ULL << 42) | (1ULL << 43) |
            (1ULL << 44) | (1ULL << 45) | (1ULL << 46);
        int p = pos[i];
        bool op = (p >= 0) && (p < 64) && (((mask >> p) & 1ULL) != 0ULL);
        g_mult[i] = op ? 8.0f : 1.0f;
    }
}

// ---------------------------------------------------------------------
// Kernel 1: per-token transform  out = tanh(X @ W^T + bias) . wa  (+extra)
// 32 tokens x 256 h per CTA, 256 threads, thread tile 4 tok x 4 f32x2-pairs.
// ---------------------------------------------------------------------
__global__ __launch_bounds__(256)
void k_transform(const float* __restrict__ X, const float* __restrict__ W,
                 const float* __restrict__ bias, const float* __restrict__ wav,
                 const float* __restrict__ extra_ptr, int which) {
    __shared__ float Ws[32 * WST];   // [kk][h], pair-aligned
    __shared__ float Xs[32 * 36];    // [tok][kk]
    __shared__ float bias_s[256];
    __shared__ float wa_s[256];

    int tid = threadIdx.x;
    int tx = tid & 31, ty = tid >> 5;
    int tok0 = blockIdx.x * 32;

    bias_s[tid] = bias ? bias[tid] : 0.0f;
    wa_s[tid] = wav[tid];

    ull acc2[4][4];
#pragma unroll
    for (int q = 0; q < 4; ++q)
#pragma unroll
        for (int m = 0; m < 4; ++m) acc2[q][m] = 0ULL;

    int kkl = tid & 31;       // k within chunk for loads
    int hb = tid >> 5;        // h base for W loads

    for (int k0 = 0; k0 < 256; k0 += 32) {
        __syncthreads();
        // W chunk: Ws[kk][h] = W[h][k0+kk]  (coalesced global, 2-way STS)
#pragma unroll
        for (int r = 0; r < 32; ++r) {
            int h = hb + r * 8;
            Ws[kkl * WST + h] = W[h * 256 + k0 + kkl];
        }
        // X chunk: Xs[tok][kk]
#pragma unroll
        for (int r = 0; r < 4; ++r) {
            int idx = r * 256 + tid;
            int tok = idx >> 5, kk = idx & 31;
            Xs[tok * 36 + kk] = X[(size_t)(tok0 + tok) * 256 + k0 + kk];
        }
        __syncthreads();
#pragma unroll 8
        for (int kk = 0; kk < 32; ++kk) {
            ull wv[4];
#pragma unroll
            for (int m = 0; m < 4; ++m)
                wv[m] = *(const ull*)(Ws + kk * WST + tx * 2 + 64 * m);
            ull xd[4];
#pragma unroll
            for (int q = 0; q < 4; ++q)
                xd[q] = pack_dup(Xs[(ty * 4 + q) * 36 + kk]);
#pragma unroll
            for (int q = 0; q < 4; ++q)
#pragma unroll
                for (int m = 0; m < 4; ++m)
                    fma2(acc2[q][m], xd[q], wv[m]);
        }
    }

    float e = extra_ptr ? extra_ptr[0] : 0.0f;
    float part[4];
#pragma unroll
    for (int q = 0; q < 4; ++q) {
        float s = 0.0f;
#pragma unroll
        for (int m = 0; m < 4; ++m) {
            int h = tx * 2 + 64 * m;
            float a0, a1;
            unpack2(acc2[q][m], a0, a1);
            s += tanhf(a0 + bias_s[h]) * wa_s[h];
            s += tanhf(a1 + bias_s[h + 1]) * wa_s[h + 1];
        }
        part[q] = s;
    }
#pragma unroll
    for (int off = 16; off; off >>= 1) {
#pragma unroll
        for (int q = 0; q < 4; ++q)
            part[q] += __shfl_xor_sync(0xffffffffu, part[q], off);
    }
    if (tx == 0) {
        float* outp = which ? g_so : g_st;
#pragma unroll
        for (int q = 0; q < 4; ++q)
            outp[tok0 + ty * 4 + q] = part[q] + e;
    }
}

// ---------------------------------------------------------------------
// Kernel 2: flash-style attention, 64 rows/CTA, 8x8 thread tile, f32x2 PV.
// ---------------------------------------------------------------------
__device__ __forceinline__ void cp16(float* s, const float* g) {
    unsigned sa = (unsigned)__cvta_generic_to_shared(s);
    asm volatile("cp.async.cg.shared.global [%0], [%1], 16;\n" ::"r"(sa), "l"(g));
}

__global__ __launch_bounds__(256, 1)
void k_attn(const float* __restrict__ V, float* __restrict__ out) {
    extern __shared__ float sm[];
    float* Vs = sm;                         // 2 * 64 * 256
    float* Ps = Vs + 2 * JT * HH;           // 64 * 68
    float* base_s = Ps + ROWS * PST;        // 2048
    float* M_s = base_s + LL;               // 64
    float* S_s = M_s + ROWS;                // 64
    float* F_s = S_s + ROWS;                // 64

    int tid = threadIdx.x;
    int tx = tid & 31, ty = tid >> 5;
    int b = blockIdx.x >> 5;
    int row0 = (blockIdx.x & 31) * ROWS;

    const float* Vg = V + (size_t)b * LL * HH;
    const float* sog = g_so + b * LL;
    const float* mug = g_mult + b * LL;

    for (int i = tid; i < LL; i += 256) base_s[i] = g_base[i];
    if (tid < ROWS) { M_s[tid] = -1e30f; S_s[tid] = 0.0f; }

    // prefetch tile 0 into buffer 0
#pragma unroll
    for (int r = 0; r < (JT * HH / 4) / 256; ++r) {
        int c = r * 256 + tid;
        cp16(Vs + c * 4, Vg + c * 4);
    }
    asm volatile("cp.async.commit_group;\n");

    // score mapping: 4 threads per row, 16 consecutive j each
    int sr = tid >> 2;              // 0..63
    int sjo = (tid & 3) * 16;
    float sti = g_st[b * LL + row0 + sr];
    int gi = row0 + sr;

    ull acc[8][4];
#pragma unroll
    for (int r = 0; r < 8; ++r)
#pragma unroll
        for (int m = 0; m < 4; ++m) acc[r][m] = 0ULL;

    __syncthreads();

    for (int t = 0; t < NT; ++t) {
        if (t) __syncthreads();
        int j0 = t * JT;

        // ---- score phase: 16 scores per thread ----
        float sov[16], muv[16];
#pragma unroll
        for (int w = 0; w < 4; ++w) {
            float4 s4 = *(const float4*)(sog + j0 + sjo + 4 * w);
            float4 m4 = *(const float4*)(mug + j0 + sjo + 4 * w);
            sov[4 * w + 0] = s4.x; sov[4 * w + 1] = s4.y;
            sov[4 * w + 2] = s4.z; sov[4 * w + 3] = s4.w;
            muv[4 * w + 0] = m4.x; muv[4 * w + 1] = m4.y;
            muv[4 * w + 2] = m4.z; muv[4 * w + 3] = m4.w;
        }
        float s[16];
        float lm = -1e30f;
#pragma unroll
        for (int u = 0; u < 16; ++u) {
            int j = j0 + sjo + u;
            int d = gi - j; d = (d < 0) ? -d : d;
            float sc = (sti + sov[u]) * base_s[d] * muv[u];
            s[u] = sc;
            lm = fmaxf(lm, sc);
        }
        lm = fmaxf(lm, __shfl_xor_sync(0xffffffffu, lm, 1));
        lm = fmaxf(lm, __shfl_xor_sync(0xffffffffu, lm, 2));
        float Mold = M_s[sr];
        float Mn = fmaxf(Mold, lm);
        float ls = 0.0f;
#pragma unroll
        for (int u = 0; u < 16; ++u) {
            float p = __expf(s[u] - Mn);
            Ps[sr * PST + sjo + u] = p;
            ls += p;
        }
        ls += __shfl_xor_sync(0xffffffffu, ls, 1);
        ls += __shfl_xor_sync(0xffffffffu, ls, 2);
        if ((tid & 3) == 0) {
            float f = __expf(Mold - Mn);
            F_s[sr] = f;
            M_s[sr] = Mn;
            S_s[sr] = S_s[sr] * f + ls;
        }

        // ---- prefetch next V tile ----
        if (t + 1 < NT) {
            float* Vn = Vs + ((t + 1) & 1) * JT * HH;
            const float* gs = Vg + (size_t)(j0 + JT) * HH;
#pragma unroll
            for (int r = 0; r < (JT * HH / 4) / 256; ++r) {
                int c = r * 256 + tid;
                cp16(Vn + c * 4, gs + c * 4);
            }
            asm volatile("cp.async.commit_group;\n");
            asm volatile("cp.async.wait_group 1;\n");
        } else {
            asm volatile("cp.async.wait_group 0;\n");
        }
        __syncthreads();  // V tile + Ps + F_s visible

        // ---- PV phase: 8 rows x 8 feats per thread, f32x2 ----
        const ulonglong2* V2 = (const ulonglong2*)(Vs + (t & 1) * JT * HH);
#pragma unroll
        for (int r = 0; r < 8; ++r) {
            ull fd = pack_dup(F_s[ty * 8 + r]);
#pragma unroll
            for (int m = 0; m < 4; ++m) mul2(acc[r][m], fd);
        }
#pragma unroll 2
        for (int j4 = 0; j4 < JT; j4 += 4) {
            float4 pr[8];
#pragma unroll
            for (int r = 0; r < 8; ++r)
                pr[r] = *(const float4*)(Ps + (ty * 8 + r) * PST + j4);
#pragma unroll
            for (int jj = 0; jj < 4; ++jj) {
                ulonglong2 va = V2[(size_t)(j4 + jj) * 64 + tx * 2];
                ulonglong2 vb = V2[(size_t)(j4 + jj) * 64 + tx * 2 + 1];
#pragma unroll
                for (int r = 0; r < 8; ++r) {
                    float p = (jj == 0) ? pr[r].x : (jj == 1) ? pr[r].y
                             : (jj == 2) ? pr[r].z : pr[r].w;
                    ull pd = pack_dup(p);
                    fma2(acc[r][0], pd, va.x);
                    fma2(acc[r][1], pd, va.y);
                    fma2(acc[r][2], pd, vb.x);
                    fma2(acc[r][3], pd, vb.y);
                }
            }
        }
    }

    // ---- epilogue: normalize and store ----
    float* Ob = out + ((size_t)b * LL + row0) * HH;
#pragma unroll
    for (int r = 0; r < 8; ++r) {
        int row = ty * 8 + r;
        float inv = 1.0f / S_s[row];
        float4 o0, o1;
        unpack2(acc[r][0], o0.x, o0.y);
        unpack2(acc[r][1], o0.z, o0.w);
        unpack2(acc[r][2], o1.x, o1.y);
        unpack2(acc[r][3], o1.z, o1.w);
        o0.x *= inv; o0.y *= inv; o0.z *= inv; o0.w *= inv;
        o1.x *= inv; o1.y *= inv; o1.z *= inv; o1.w *= inv;
        float4* O4 = (float4*)(Ob + (size_t)row * HH + tx * 8);
        O4[0] = o0;
        O4[1] = o1;
    }
}

// ---------------------------------------------------------------------
extern "C" void kernel_launch(void* const* d_in, const int* in_sizes, int n_in,
                              void* d_out, int out_size) {
    const float* opinion = (const float*)d_in[0];
    const float* text    = (const float*)d_in[1];
    const int*   pos     = (const int*)d_in[2];
    const float* Wt      = (const float*)d_in[3];
    const float* bt      = (const float*)d_in[4];
    const float* Wo      = (const float*)d_in[5];
    const float* wa      = (const float*)d_in[6];
    const float* ba      = (const float*)d_in[7];
    float* out = (float*)d_out;

    const int attn_smem = (2 * JT * HH + ROWS * PST + LL + 3 * ROWS) * 4;
    cudaFuncSetAttribute(k_attn, cudaFuncAttributeMaxDynamicSharedMemorySize,
                         attn_smem);

    k_base_mult<<<(BB * LL + 255) / 256, 256>>>(pos);
    k_transform<<<BB * LL / 32, 256>>>(text, Wt, bt, wa, nullptr, 0);
    k_transform<<<BB * LL / 32, 256>>>(opinion, Wo, nullptr, wa + HH, ba, 1);
    k_attn<<<BB * (LL / ROWS), 256, attn_smem>>>(opinion, out);
}